// round 1
// baseline (speedup 1.0000x reference)
#include <cuda_runtime.h>
#include <math.h>

// Problem constants
#define NTOK  65536          // real tokens: T(2)*N(256) windows * 128 sq
#define NWIN  512            // T*N
#define SQ    128            // V*TT*NN*DD
#define SKV   512            // V*T2*NN*D2
#define F     64
#define ATT   128
#define HDIM  32
#define NHEAD 4

// Scratch (device globals — no runtime allocation allowed)
__device__ float g_h[NTOK * F];      // LN output, token-major
__device__ float g_q[NTOK * ATT];
__device__ float g_k[NTOK * ATT];
__device__ float g_v[NTOK * ATT];
__device__ float g_o[NTOK * ATT];

// token = Tt*(256*128) + n*128 + v*64 + tt*16 + nn*4 + dd
// x layout: (V=2, T*TT=8, N*NN=1024, D*DD=4, F=64)
__device__ __forceinline__ int x_off(int tok, int f) {
    int dd = tok & 3;
    int nn = (tok >> 2) & 3;
    int tt = (tok >> 4) & 3;
    int v  = (tok >> 6) & 1;
    int n  = (tok >> 7) & 255;
    int Tt = (tok >> 15) & 1;
    return ((((v * 8 + Tt * 4 + tt) * 1024) + (n * 4 + nn)) * 4 + dd) * 64 + f;
}

__device__ __forceinline__ float wsum(float v) {
#pragma unroll
    for (int o = 16; o; o >>= 1) v += __shfl_xor_sync(0xffffffffu, v, o);
    return v;
}

// ---------------- Kernel 1: LayerNorm (1 warp per token) ----------------
__global__ __launch_bounds__(256) void k_ln(const float* __restrict__ x,
                                            const float* __restrict__ s,
                                            const float* __restrict__ b) {
    int tok  = blockIdx.x * 8 + (threadIdx.x >> 5);
    int lane = threadIdx.x & 31;
    float x0 = x[x_off(tok, lane)];
    float x1 = x[x_off(tok, lane + 32)];
    float m = wsum(x0 + x1) * (1.0f / 64.0f);
    float d0 = x0 - m, d1 = x1 - m;
    float var = wsum(d0 * d0 + d1 * d1) * (1.0f / 64.0f);
    float inv = rsqrtf(var + 1e-5f);
    g_h[tok * 64 + lane]      = d0 * inv * s[lane]      + b[lane];
    g_h[tok * 64 + lane + 32] = d1 * inv * s[lane + 32] + b[lane + 32];
}

// ------------- Kernel 2: fused q/k/v projection (16 tok / block) -------------
// 384 threads: a<128 -> q column a; a>=128 -> kv column a-128 (k if <128 else v)
__global__ __launch_bounds__(384) void k_proj(const float* __restrict__ Wq,
                                              const float* __restrict__ Wkv,
                                              const float* __restrict__ bkv) {
    __shared__ float hs[16][64];
    int t0 = blockIdx.x * 16;
    for (int i = threadIdx.x; i < 16 * 64; i += 384)
        hs[i >> 6][i & 63] = g_h[t0 * 64 + i];
    __syncthreads();

    int a = threadIdx.x;
    float acc[16];
#pragma unroll
    for (int t = 0; t < 16; t++) acc[t] = 0.0f;

    if (a < 128) {
        for (int f = 0; f < 64; f++) {
            float wv = Wq[f * 128 + a];
#pragma unroll
            for (int t = 0; t < 16; t++) acc[t] += hs[t][f] * wv;
        }
#pragma unroll
        for (int t = 0; t < 16; t++) g_q[(t0 + t) * 128 + a] = acc[t];
    } else {
        int c = a - 128;  // 0..255
        for (int f = 0; f < 64; f++) {
            float wv = Wkv[f * 256 + c];
#pragma unroll
            for (int t = 0; t < 16; t++) acc[t] += hs[t][f] * wv;
        }
        float bb = bkv[c];
        if (c < 128) {
#pragma unroll
            for (int t = 0; t < 16; t++) g_k[(t0 + t) * 128 + c] = acc[t] + bb;
        } else {
#pragma unroll
            for (int t = 0; t < 16; t++) g_v[(t0 + t) * 128 + (c - 128)] = acc[t] + bb;
        }
    }
}

// ------------- Kernel 3: attention (block = window*head, 128 threads) -------------
// Online softmax over 16 tiles of 32 kv slots. Halo decode on the fly:
// pad slots use k=bkv[:128], v=bkv[128:] (depth halo is pure zero-pad since D=1).
__global__ __launch_bounds__(128) void k_attn(const float* __restrict__ bkv) {
    __shared__ float ks[32][33];
    __shared__ float vs[32][33];
    int w    = blockIdx.x >> 2;
    int head = blockIdx.x & 3;
    int Tt   = w >> 8;
    int n    = w & 255;
    int sq   = threadIdx.x;

    float q[32];
    const float* qp = &g_q[(w * 128 + sq) * 128 + head * 32];
#pragma unroll
    for (int i = 0; i < 32; i++) q[i] = qp[i];

    float m = -1e30f, l = 0.0f;
    float acc[32];
#pragma unroll
    for (int i = 0; i < 32; i++) acc[i] = 0.0f;

    int j  = threadIdx.x >> 2;        // kv row this thread loads (0..31)
    int i0 = (threadIdx.x & 3) * 8;   // channel chunk (0,8,16,24)

    for (int tile = 0; tile < 16; tile++) {
        __syncthreads();
        // ---- cooperative load of 32 kv rows with halo decode ----
        {
            int skv = tile * 32 + j;
            int d2  = skv & 7;
            int nn  = (skv >> 3) & 3;
            int t2  = (skv >> 5) & 7;
            int v   = (skv >> 8) & 1;
            bool pad = (d2 < 2) || (d2 >= 6);
            int Ttp = Tt, tt;
            if (t2 < 2)      { Ttp = Tt - 1; tt = t2 + 2; }
            else if (t2 >= 6){ Ttp = Tt + 1; tt = t2 - 6; }
            else             { tt = t2 - 2; }
            if (Ttp < 0 || Ttp >= 2) pad = true;
            if (pad) {
#pragma unroll
                for (int ii = 0; ii < 8; ii++) {
                    ks[j][i0 + ii] = bkv[head * 32 + i0 + ii];
                    vs[j][i0 + ii] = bkv[128 + head * 32 + i0 + ii];
                }
            } else {
                int tokp = ((Ttp * 256 + n) * 128) + ((v * 4 + tt) * 4 + nn) * 4 + (d2 - 2);
                const float* kp = &g_k[tokp * 128 + head * 32];
                const float* vp = &g_v[tokp * 128 + head * 32];
#pragma unroll
                for (int ii = 0; ii < 8; ii++) {
                    ks[j][i0 + ii] = kp[i0 + ii];
                    vs[j][i0 + ii] = vp[i0 + ii];
                }
            }
        }
        __syncthreads();

        // ---- scores for this tile ----
        float sc[32];
#pragma unroll
        for (int j2 = 0; j2 < 32; j2++) {
            float s_ = 0.0f;
#pragma unroll
            for (int i = 0; i < 32; i++) s_ += q[i] * ks[j2][i];
            sc[j2] = s_ * 0.17677669529663687f;  // 1/sqrt(32)
        }
        float mt = m;
#pragma unroll
        for (int j2 = 0; j2 < 32; j2++) mt = fmaxf(mt, sc[j2]);
        float corr = __expf(m - mt);
        m = mt;
        l *= corr;
#pragma unroll
        for (int i = 0; i < 32; i++) acc[i] *= corr;
#pragma unroll
        for (int j2 = 0; j2 < 32; j2++) {
            float e = __expf(sc[j2] - m);
            l += e;
#pragma unroll
            for (int i = 0; i < 32; i++) acc[i] += e * vs[j2][i];
        }
    }

    float invl = 1.0f / l;
    float* op = &g_o[(w * 128 + sq) * 128 + head * 32];
#pragma unroll
    for (int i = 0; i < 32; i++) op[i] = acc[i] * invl;
}

// ------------- Kernel 4: epilogue (Wo + res + LN2 + MLP + res + transpose out) -------------
__global__ __launch_bounds__(256) void k_epi(const float* __restrict__ x,
                                             const float* __restrict__ Wo,
                                             const float* __restrict__ bo,
                                             const float* __restrict__ gamma,
                                             const float* __restrict__ ln2s,
                                             const float* __restrict__ ln2b,
                                             const float* __restrict__ W1,
                                             const float* __restrict__ b1,
                                             const float* __restrict__ W2,
                                             const float* __restrict__ b2,
                                             const float* __restrict__ gmlp,
                                             float* __restrict__ out) {
    __shared__ float os[16][128];
    __shared__ float toks[16][64];
    __shared__ float h2s[16][64];
    __shared__ float gs[16][128];
    int t0 = blockIdx.x * 16;

    for (int i = threadIdx.x; i < 16 * 128; i += 256)
        os[i >> 7][i & 127] = g_o[t0 * 128 + i];
    for (int i = threadIdx.x; i < 16 * 64; i += 256) {
        int t = i >> 6, f = i & 63;
        toks[t][f] = x[x_off(t0 + t, f)];
    }
    __syncthreads();

    // upd = o @ Wo + bo; tok += gamma * upd
    {
        int g = threadIdx.x >> 6, f = threadIdx.x & 63;
        float acc[4] = {0.f, 0.f, 0.f, 0.f};
        for (int a = 0; a < 128; a++) {
            float wv = Wo[a * 64 + f];
#pragma unroll
            for (int t = 0; t < 4; t++) acc[t] += os[g * 4 + t][a] * wv;
        }
        float bof = bo[f], gm = gamma[f];
#pragma unroll
        for (int t = 0; t < 4; t++) toks[g * 4 + t][f] += gm * (acc[t] + bof);
    }
    __syncthreads();

    // LN2 (1 warp per 2 tokens)
    {
        int wid = threadIdx.x >> 5, lane = threadIdx.x & 31;
#pragma unroll
        for (int tt = 0; tt < 2; tt++) {
            int t = wid * 2 + tt;
            float a0 = toks[t][lane], a1 = toks[t][lane + 32];
            float mm = wsum(a0 + a1) * (1.0f / 64.0f);
            float d0 = a0 - mm, d1 = a1 - mm;
            float var = wsum(d0 * d0 + d1 * d1) * (1.0f / 64.0f);
            float inv = rsqrtf(var + 1e-5f);
            h2s[t][lane]      = d0 * inv * ln2s[lane]      + ln2b[lane];
            h2s[t][lane + 32] = d1 * inv * ln2s[lane + 32] + ln2b[lane + 32];
        }
    }
    __syncthreads();

    // hidden = gelu(h2 @ W1 + b1)
    {
        int g = threadIdx.x >> 7, a = threadIdx.x & 127;
        float acc[8];
#pragma unroll
        for (int t = 0; t < 8; t++) acc[t] = 0.0f;
        for (int f = 0; f < 64; f++) {
            float wv = W1[f * 128 + a];
#pragma unroll
            for (int t = 0; t < 8; t++) acc[t] += h2s[g * 8 + t][f] * wv;
        }
        float bb = b1[a];
#pragma unroll
        for (int t = 0; t < 8; t++) {
            float z = acc[t] + bb;
            // tanh-approx gelu (JAX default)
            float g_ = 0.5f * z * (1.0f + tanhf(0.7978845608028654f * (z + 0.044715f * z * z * z)));
            gs[g * 8 + t][a] = g_;
        }
    }
    __syncthreads();

    // out = tok + gamma_mlp * (hidden @ W2 + b2), transposed back to x layout
    {
        int g = threadIdx.x >> 6, f = threadIdx.x & 63;
        float acc[4] = {0.f, 0.f, 0.f, 0.f};
        for (int a = 0; a < 128; a++) {
            float wv = W2[a * 64 + f];
#pragma unroll
            for (int t = 0; t < 4; t++) acc[t] += gs[g * 4 + t][a] * wv;
        }
        float bb = b2[f], gm = gmlp[f];
#pragma unroll
        for (int t = 0; t < 4; t++) {
            int tok = t0 + g * 4 + t;
            out[x_off(tok, f)] = toks[g * 4 + t][f] + gm * (acc[t] + bb);
        }
    }
}

extern "C" void kernel_launch(void* const* d_in, const int* in_sizes, int n_in,
                              void* d_out, int out_size) {
    const float* x     = (const float*)d_in[0];
    const float* ln1_s = (const float*)d_in[1];
    const float* ln1_b = (const float*)d_in[2];
    const float* Wq    = (const float*)d_in[3];
    const float* Wkv   = (const float*)d_in[4];
    const float* bkv   = (const float*)d_in[5];
    const float* Wo    = (const float*)d_in[6];
    const float* bo    = (const float*)d_in[7];
    const float* gamma = (const float*)d_in[8];
    const float* ln2s  = (const float*)d_in[9];
    const float* ln2b  = (const float*)d_in[10];
    const float* W1    = (const float*)d_in[11];
    const float* b1    = (const float*)d_in[12];
    const float* W2    = (const float*)d_in[13];
    const float* b2    = (const float*)d_in[14];
    const float* gmlp  = (const float*)d_in[15];
    float* out = (float*)d_out;

    k_ln  <<<NTOK / 8, 256>>>(x, ln1_s, ln1_b);
    k_proj<<<NTOK / 16, 384>>>(Wq, Wkv, bkv);
    k_attn<<<NWIN * NHEAD, 128>>>(bkv);
    k_epi <<<NTOK / 16, 256>>>(x, Wo, bo, gamma, ln2s, ln2b, W1, b1, W2, b2, gmlp, out);
}

// round 2
// speedup vs baseline: 1.9852x; 1.9852x over previous
#include <cuda_runtime.h>
#include <cuda_bf16.h>
#include <math.h>

// Problem constants
#define NTOK  65536          // real tokens
#define NWIN  512            // T*N windows
#define F     64
#define ATT   128
#define NHEAD 4
#define SCALE 0.17677669529663687f   // 1/sqrt(32)

// Scratch (device globals — no runtime allocation allowed)
__device__ __nv_bfloat16 g_q[NTOK * ATT];
__device__ __nv_bfloat16 g_k[NTOK * ATT];
__device__ __nv_bfloat16 g_v[NTOK * ATT];
__device__ float         g_o[NTOK * ATT];

// token = Tt*(256*128) + n*128 + v*64 + tt*16 + nn*4 + dd
__device__ __forceinline__ int x_off(int tok, int f) {
    int dd = tok & 3;
    int nn = (tok >> 2) & 3;
    int tt = (tok >> 4) & 3;
    int v  = (tok >> 6) & 1;
    int n  = (tok >> 7) & 255;
    int Tt = (tok >> 15) & 1;
    return ((((v * 8 + Tt * 4 + tt) * 1024) + (n * 4 + nn)) * 4 + dd) * 64 + f;
}

__device__ __forceinline__ unsigned pack_bf2(float a, float b) {
    __nv_bfloat162 h = __floats2bfloat162_rn(a, b);
    return *(unsigned*)&h;
}

__device__ __forceinline__ void mma_bf16(float c[4], const unsigned a[4], const unsigned b[2]) {
    asm volatile("mma.sync.aligned.m16n8k16.row.col.f32.bf16.bf16.f32 "
                 "{%0,%1,%2,%3}, {%4,%5,%6,%7}, {%8,%9}, {%0,%1,%2,%3};"
                 : "+f"(c[0]), "+f"(c[1]), "+f"(c[2]), "+f"(c[3])
                 : "r"(a[0]), "r"(a[1]), "r"(a[2]), "r"(a[3]),
                   "r"(b[0]), "r"(b[1]));
}

__device__ __forceinline__ float wsum(float v) {
#pragma unroll
    for (int o = 16; o; o >>= 1) v += __shfl_xor_sync(0xffffffffu, v, o);
    return v;
}

// ================= Kernel 1: fused LN1 + qkv projection (bf16 MMA) =================
// Block = 128 tokens (one window), 256 threads = 8 warps, each warp owns 48 output cols.
#define HSTR 72
#define WSTR 72
#define LNPROJ_SMEM ((128 * HSTR + 384 * WSTR) * (int)sizeof(__nv_bfloat16))

__global__ __launch_bounds__(256) void k_lnproj(const float* __restrict__ x,
                                                const float* __restrict__ ln1s,
                                                const float* __restrict__ ln1b,
                                                const float* __restrict__ Wq,
                                                const float* __restrict__ Wkv,
                                                const float* __restrict__ bkv) {
    extern __shared__ __nv_bfloat16 sm[];
    __nv_bfloat16* hs = sm;                  // [128][HSTR]
    __nv_bfloat16* Wt = sm + 128 * HSTR;     // [384][WSTR]  (Wt[a][f])
    int t0 = blockIdx.x * 128;
    int tid = threadIdx.x;

    if (tid < 128) {
        const float* xp = &x[x_off(t0 + tid, 0)];
        float v[64];
        float sum = 0.f;
#pragma unroll
        for (int i = 0; i < 16; i++) {
            float4 a = *(const float4*)(xp + 4 * i);
            v[4 * i] = a.x; v[4 * i + 1] = a.y; v[4 * i + 2] = a.z; v[4 * i + 3] = a.w;
            sum += a.x + a.y + a.z + a.w;
        }
        float mean = sum * (1.f / 64.f), var = 0.f;
#pragma unroll
        for (int i = 0; i < 64; i++) { float d = v[i] - mean; var += d * d; }
        float inv = rsqrtf(var * (1.f / 64.f) + 1e-5f);
#pragma unroll
        for (int i = 0; i < 64; i++)
            hs[tid * HSTR + i] = __float2bfloat16((v[i] - mean) * inv * ln1s[i] + ln1b[i]);
    }
    for (int i = tid; i < 384 * 64; i += 256) {
        int a = i >> 6, f = i & 63;
        float w = (a < 128) ? Wq[f * 128 + a] : Wkv[f * 256 + a - 128];
        Wt[a * WSTR + f] = __float2bfloat16(w);
    }
    __syncthreads();

    int wid = tid >> 5, lane = tid & 31;
    int g = lane >> 2, tq = lane & 3;
    int nbase = wid * 48;
    for (int m = 0; m < 8; m++) {
        unsigned af[4][4];
        int r0 = m * 16 + g;
#pragma unroll
        for (int kc = 0; kc < 4; kc++) {
            af[kc][0] = *(const unsigned*)&hs[r0 * HSTR + kc * 16 + 2 * tq];
            af[kc][1] = *(const unsigned*)&hs[(r0 + 8) * HSTR + kc * 16 + 2 * tq];
            af[kc][2] = *(const unsigned*)&hs[r0 * HSTR + kc * 16 + 2 * tq + 8];
            af[kc][3] = *(const unsigned*)&hs[(r0 + 8) * HSTR + kc * 16 + 2 * tq + 8];
        }
#pragma unroll
        for (int nt = 0; nt < 6; nt++) {
            float c[4] = {0.f, 0.f, 0.f, 0.f};
            int col = nbase + nt * 8 + g;
#pragma unroll
            for (int kc = 0; kc < 4; kc++) {
                unsigned bf[2];
                bf[0] = *(const unsigned*)&Wt[col * WSTR + kc * 16 + 2 * tq];
                bf[1] = *(const unsigned*)&Wt[col * WSTR + kc * 16 + 2 * tq + 8];
                mma_bf16(c, af[kc], bf);
            }
            int a0 = nbase + nt * 8 + 2 * tq;
            int row0 = t0 + m * 16 + g;
            if (a0 < 128) {
                *(unsigned*)&g_q[row0 * 128 + a0]       = pack_bf2(c[0], c[1]);
                *(unsigned*)&g_q[(row0 + 8) * 128 + a0] = pack_bf2(c[2], c[3]);
            } else {
                float b0 = bkv[a0 - 128], b1 = bkv[a0 - 127];
                int cc = a0 - 128;
                if (cc < 128) {
                    *(unsigned*)&g_k[row0 * 128 + cc]       = pack_bf2(c[0] + b0, c[1] + b1);
                    *(unsigned*)&g_k[(row0 + 8) * 128 + cc] = pack_bf2(c[2] + b0, c[3] + b1);
                } else {
                    *(unsigned*)&g_v[row0 * 128 + cc - 128]       = pack_bf2(c[0] + b0, c[1] + b1);
                    *(unsigned*)&g_v[(row0 + 8) * 128 + cc - 128] = pack_bf2(c[2] + b0, c[3] + b1);
                }
            }
        }
    }
}

// ================= Kernel 2: attention (warp MMA flash) =================
// Block = (window, head), 128 threads = 4 warps, each warp owns 32 q rows.
#define QSTR  36
#define KSTR  36
#define VSTR  72
#define PSTR2 72

__global__ __launch_bounds__(128, 4) void k_attn(const float* __restrict__ bkv) {
    __shared__ __nv_bfloat16 Qs[128 * QSTR];
    __shared__ __nv_bfloat16 Ks[64 * KSTR];
    __shared__ __nv_bfloat16 Vt[32 * VSTR];       // Vt[ch][kv]
    __shared__ __nv_bfloat16 Sb[4 * 32 * PSTR2];  // per-warp S (reused as P)

    int w = blockIdx.x >> 2, head = blockIdx.x & 3;
    int Tt = w >> 8, n = w & 255;
    int tid = threadIdx.x, wid = tid >> 5, lane = tid & 31;
    int g = lane >> 2, tq = lane & 3;

    // load Q (one row per thread)
    {
        const __nv_bfloat16* qp = &g_q[(w * 128 + tid) * 128 + head * 32];
#pragma unroll
        for (int c = 0; c < 32; c += 2)
            *(unsigned*)&Qs[tid * QSTR + c] = *(const unsigned*)&qp[c];
    }
    __syncthreads();

    unsigned qf[2][2][4];
#pragma unroll
    for (int m = 0; m < 2; m++) {
        int r0 = wid * 32 + m * 16 + g;
#pragma unroll
        for (int kc = 0; kc < 2; kc++) {
            qf[m][kc][0] = *(const unsigned*)&Qs[r0 * QSTR + kc * 16 + 2 * tq];
            qf[m][kc][1] = *(const unsigned*)&Qs[(r0 + 8) * QSTR + kc * 16 + 2 * tq];
            qf[m][kc][2] = *(const unsigned*)&Qs[r0 * QSTR + kc * 16 + 2 * tq + 8];
            qf[m][kc][3] = *(const unsigned*)&Qs[(r0 + 8) * QSTR + kc * 16 + 2 * tq + 8];
        }
    }

    __nv_bfloat16* Sp = &Sb[wid * 32 * PSTR2];
    float O[2][4][4];
#pragma unroll
    for (int m = 0; m < 2; m++)
#pragma unroll
        for (int nt = 0; nt < 4; nt++)
#pragma unroll
            for (int i = 0; i < 4; i++) O[m][nt][i] = 0.f;

    float mrow = -1e30f, lrow = 0.f;
    int jrow = tid >> 1, halfc = (tid & 1) * 16;

    for (int tile = 0; tile < 8; tile++) {
        __syncthreads();
        // ---- load 64 kv rows with halo decode; V transposed ----
        {
            int skv = tile * 64 + jrow;
            int d2 = skv & 7, nn2 = (skv >> 3) & 3, t2 = (skv >> 5) & 7, vv = (skv >> 8) & 1;
            bool pad = (d2 < 2) || (d2 >= 6);
            int Ttp = Tt, tt;
            if (t2 < 2)       { Ttp = Tt - 1; tt = t2 + 2; }
            else if (t2 >= 6) { Ttp = Tt + 1; tt = t2 - 6; }
            else              { tt = t2 - 2; }
            if (Ttp < 0 || Ttp >= 2) pad = true;
            if (pad) {
#pragma unroll
                for (int c = 0; c < 16; c++) {
                    Ks[jrow * KSTR + halfc + c]   = __float2bfloat16(bkv[head * 32 + halfc + c]);
                    Vt[(halfc + c) * VSTR + jrow] = __float2bfloat16(bkv[128 + head * 32 + halfc + c]);
                }
            } else {
                int tokp = ((Ttp * 256 + n) * 128) + ((vv * 4 + tt) * 4 + nn2) * 4 + (d2 - 2);
                const __nv_bfloat16* kp = &g_k[tokp * 128 + head * 32 + halfc];
                const __nv_bfloat16* vp = &g_v[tokp * 128 + head * 32 + halfc];
#pragma unroll
                for (int c = 0; c < 16; c += 2)
                    *(unsigned*)&Ks[jrow * KSTR + halfc + c] = *(const unsigned*)&kp[c];
#pragma unroll
                for (int c = 0; c < 16; c++)
                    Vt[(halfc + c) * VSTR + jrow] = vp[c];
            }
        }
        __syncthreads();

        // ---- S = Q K^T (bf16 out to per-warp smem) ----
#pragma unroll
        for (int m = 0; m < 2; m++)
#pragma unroll
            for (int nt = 0; nt < 8; nt++) {
                float c[4] = {0.f, 0.f, 0.f, 0.f};
#pragma unroll
                for (int kc = 0; kc < 2; kc++) {
                    unsigned bf[2];
                    bf[0] = *(const unsigned*)&Ks[(nt * 8 + g) * KSTR + kc * 16 + 2 * tq];
                    bf[1] = *(const unsigned*)&Ks[(nt * 8 + g) * KSTR + kc * 16 + 2 * tq + 8];
                    mma_bf16(c, qf[m][kc], bf);
                }
                int r0 = m * 16 + g, c0 = nt * 8 + 2 * tq;
                *(unsigned*)&Sp[r0 * PSTR2 + c0]       = pack_bf2(c[0], c[1]);
                *(unsigned*)&Sp[(r0 + 8) * PSTR2 + c0] = pack_bf2(c[2], c[3]);
            }
        __syncwarp();

        // ---- row softmax (row = lane), in-place S -> P ----
        uint4 chunk[8];
        const uint4* srow = (const uint4*)&Sp[lane * PSTR2];
        float rawmax = -1e30f;
#pragma unroll
        for (int c8 = 0; c8 < 8; c8++) {
            chunk[c8] = srow[c8];
            const unsigned* u = (const unsigned*)&chunk[c8];
#pragma unroll
            for (int p = 0; p < 4; p++) {
                float2 f2 = __bfloat1622float2(*(const __nv_bfloat162*)&u[p]);
                rawmax = fmaxf(rawmax, fmaxf(f2.x, f2.y));
            }
        }
        float mt = fmaxf(mrow, rawmax * SCALE);
        float corr = __expf(mrow - mt);
        mrow = mt;
        float lsum = 0.f;
        uint4* wrow = (uint4*)&Sp[lane * PSTR2];
#pragma unroll
        for (int c8 = 0; c8 < 8; c8++) {
            const unsigned* u = (const unsigned*)&chunk[c8];
            unsigned outw[4];
#pragma unroll
            for (int p = 0; p < 4; p++) {
                float2 f2 = __bfloat1622float2(*(const __nv_bfloat162*)&u[p]);
                float e0 = __expf(f2.x * SCALE - mt);
                float e1 = __expf(f2.y * SCALE - mt);
                lsum += e0 + e1;
                outw[p] = pack_bf2(e0, e1);
            }
            wrow[c8] = *(const uint4*)outw;
        }
        lrow = lrow * corr + lsum;

        // rescale O by per-row correction
#pragma unroll
        for (int m = 0; m < 2; m++) {
            float cr0 = __shfl_sync(0xffffffffu, corr, m * 16 + g);
            float cr1 = __shfl_sync(0xffffffffu, corr, m * 16 + g + 8);
#pragma unroll
            for (int nt = 0; nt < 4; nt++) {
                O[m][nt][0] *= cr0; O[m][nt][1] *= cr0;
                O[m][nt][2] *= cr1; O[m][nt][3] *= cr1;
            }
        }
        __syncwarp();

        // ---- O += P V ----
#pragma unroll
        for (int kc = 0; kc < 4; kc++) {
            unsigned pf[2][4];
#pragma unroll
            for (int m = 0; m < 2; m++) {
                int r0 = m * 16 + g;
                pf[m][0] = *(const unsigned*)&Sp[r0 * PSTR2 + kc * 16 + 2 * tq];
                pf[m][1] = *(const unsigned*)&Sp[(r0 + 8) * PSTR2 + kc * 16 + 2 * tq];
                pf[m][2] = *(const unsigned*)&Sp[r0 * PSTR2 + kc * 16 + 2 * tq + 8];
                pf[m][3] = *(const unsigned*)&Sp[(r0 + 8) * PSTR2 + kc * 16 + 2 * tq + 8];
            }
#pragma unroll
            for (int nt = 0; nt < 4; nt++) {
                unsigned bf[2];
                bf[0] = *(const unsigned*)&Vt[(nt * 8 + g) * VSTR + kc * 16 + 2 * tq];
                bf[1] = *(const unsigned*)&Vt[(nt * 8 + g) * VSTR + kc * 16 + 2 * tq + 8];
#pragma unroll
                for (int m = 0; m < 2; m++)
                    mma_bf16(O[m][nt], pf[m], bf);
            }
        }
    }

    float invl = 1.f / lrow;
#pragma unroll
    for (int m = 0; m < 2; m++) {
        float i0 = __shfl_sync(0xffffffffu, invl, m * 16 + g);
        float i1 = __shfl_sync(0xffffffffu, invl, m * 16 + g + 8);
        int sq0 = wid * 32 + m * 16 + g;
#pragma unroll
        for (int nt = 0; nt < 4; nt++) {
            int ch = nt * 8 + 2 * tq;
            float2 v0 = make_float2(O[m][nt][0] * i0, O[m][nt][1] * i0);
            float2 v1 = make_float2(O[m][nt][2] * i1, O[m][nt][3] * i1);
            *(float2*)&g_o[(w * 128 + sq0) * 128 + head * 32 + ch]       = v0;
            *(float2*)&g_o[(w * 128 + sq0 + 8) * 128 + head * 32 + ch]   = v1;
        }
    }
}

// ================= Kernel 3: epilogue =================
__global__ __launch_bounds__(256) void k_epi(const float* __restrict__ x,
                                             const float* __restrict__ Wo,
                                             const float* __restrict__ bo,
                                             const float* __restrict__ gamma,
                                             const float* __restrict__ ln2s,
                                             const float* __restrict__ ln2b,
                                             const float* __restrict__ W1,
                                             const float* __restrict__ b1,
                                             const float* __restrict__ W2,
                                             const float* __restrict__ b2,
                                             const float* __restrict__ gmlp,
                                             float* __restrict__ out) {
    __shared__ float os[16][128];
    __shared__ float toks[16][64];
    __shared__ float h2s[16][64];
    __shared__ float gs[16][128];
    int t0 = blockIdx.x * 16;

    for (int i = threadIdx.x; i < 16 * 128; i += 256)
        os[i >> 7][i & 127] = g_o[t0 * 128 + i];
    for (int i = threadIdx.x; i < 16 * 64; i += 256) {
        int t = i >> 6, f = i & 63;
        toks[t][f] = x[x_off(t0 + t, f)];
    }
    __syncthreads();

    // upd = o @ Wo + bo; tok += gamma * upd
    {
        int gg = threadIdx.x >> 6, f = threadIdx.x & 63;
        float acc[4] = {0.f, 0.f, 0.f, 0.f};
#pragma unroll 4
        for (int a = 0; a < 128; a += 4) {
            float w0 = Wo[a * 64 + f], w1 = Wo[(a + 1) * 64 + f];
            float w2 = Wo[(a + 2) * 64 + f], w3 = Wo[(a + 3) * 64 + f];
#pragma unroll
            for (int t = 0; t < 4; t++) {
                float4 o4 = *(const float4*)&os[gg * 4 + t][a];
                acc[t] += o4.x * w0 + o4.y * w1 + o4.z * w2 + o4.w * w3;
            }
        }
        float bof = bo[f], gm = gamma[f];
#pragma unroll
        for (int t = 0; t < 4; t++) toks[gg * 4 + t][f] += gm * (acc[t] + bof);
    }
    __syncthreads();

    // LN2
    {
        int wid = threadIdx.x >> 5, lane = threadIdx.x & 31;
#pragma unroll
        for (int tt = 0; tt < 2; tt++) {
            int t = wid * 2 + tt;
            float a0 = toks[t][lane], a1 = toks[t][lane + 32];
            float mm = wsum(a0 + a1) * (1.0f / 64.0f);
            float d0 = a0 - mm, d1 = a1 - mm;
            float var = wsum(d0 * d0 + d1 * d1) * (1.0f / 64.0f);
            float inv = rsqrtf(var + 1e-5f);
            h2s[t][lane]      = d0 * inv * ln2s[lane]      + ln2b[lane];
            h2s[t][lane + 32] = d1 * inv * ln2s[lane + 32] + ln2b[lane + 32];
        }
    }
    __syncthreads();

    // hidden = gelu(h2 @ W1 + b1)
    {
        int gp = threadIdx.x >> 7, a = threadIdx.x & 127;
        float acc[8];
#pragma unroll
        for (int t = 0; t < 8; t++) acc[t] = 0.0f;
#pragma unroll 4
        for (int f = 0; f < 64; f += 4) {
            float w0 = W1[f * 128 + a], w1 = W1[(f + 1) * 128 + a];
            float w2 = W1[(f + 2) * 128 + a], w3 = W1[(f + 3) * 128 + a];
#pragma unroll
            for (int t = 0; t < 8; t++) {
                float4 h4 = *(const float4*)&h2s[gp * 8 + t][f];
                acc[t] += h4.x * w0 + h4.y * w1 + h4.z * w2 + h4.w * w3;
            }
        }
        float bb = b1[a];
#pragma unroll
        for (int t = 0; t < 8; t++) {
            float z = acc[t] + bb;
            float g_ = 0.5f * z * (1.0f + tanhf(0.7978845608028654f * (z + 0.044715f * z * z * z)));
            gs[gp * 8 + t][a] = g_;
        }
    }
    __syncthreads();

    // out = tok + gamma_mlp * (hidden @ W2 + b2)
    {
        int gg = threadIdx.x >> 6, f = threadIdx.x & 63;
        float acc[4] = {0.f, 0.f, 0.f, 0.f};
#pragma unroll 4
        for (int a = 0; a < 128; a += 4) {
            float w0 = W2[a * 64 + f], w1 = W2[(a + 1) * 64 + f];
            float w2 = W2[(a + 2) * 64 + f], w3 = W2[(a + 3) * 64 + f];
#pragma unroll
            for (int t = 0; t < 4; t++) {
                float4 g4 = *(const float4*)&gs[gg * 4 + t][a];
                acc[t] += g4.x * w0 + g4.y * w1 + g4.z * w2 + g4.w * w3;
            }
        }
        float bb = b2[f], gm = gmlp[f];
#pragma unroll
        for (int t = 0; t < 4; t++) {
            int tok = t0 + gg * 4 + t;
            out[x_off(tok, f)] = toks[gg * 4 + t][f] + gm * (acc[t] + bb);
        }
    }
}

extern "C" void kernel_launch(void* const* d_in, const int* in_sizes, int n_in,
                              void* d_out, int out_size) {
    const float* x     = (const float*)d_in[0];
    const float* ln1_s = (const float*)d_in[1];
    const float* ln1_b = (const float*)d_in[2];
    const float* Wq    = (const float*)d_in[3];
    const float* Wkv   = (const float*)d_in[4];
    const float* bkv   = (const float*)d_in[5];
    const float* Wo    = (const float*)d_in[6];
    const float* bo    = (const float*)d_in[7];
    const float* gamma = (const float*)d_in[8];
    const float* ln2s  = (const float*)d_in[9];
    const float* ln2b  = (const float*)d_in[10];
    const float* W1    = (const float*)d_in[11];
    const float* b1    = (const float*)d_in[12];
    const float* W2    = (const float*)d_in[13];
    const float* b2    = (const float*)d_in[14];
    const float* gmlp  = (const float*)d_in[15];
    float* out = (float*)d_out;

    cudaFuncSetAttribute(k_lnproj, cudaFuncAttributeMaxDynamicSharedMemorySize, LNPROJ_SMEM);

    k_lnproj<<<NTOK / 128, 256, LNPROJ_SMEM>>>(x, ln1_s, ln1_b, Wq, Wkv, bkv);
    k_attn  <<<NWIN * NHEAD, 128>>>(bkv);
    k_epi   <<<NTOK / 16, 256>>>(x, Wo, bo, gamma, ln2s, ln2b, W1, b1, W2, b2, gmlp, out);
}

// round 3
// speedup vs baseline: 4.5353x; 2.2846x over previous
#include <cuda_runtime.h>
#include <cuda_bf16.h>
#include <math.h>

#define NTOK  65536
#define NWIN  512
#define NHEAD 4
#define SCALE 0.17677669529663687f   // 1/sqrt(32)

// Scratch (device globals)
__device__ __nv_bfloat16 g_q[NTOK * 128];
__device__ __nv_bfloat16 g_k[NTOK * 128];
__device__ __nv_bfloat16 g_v[NTOK * 128];
__device__ __nv_bfloat16 g_o[NTOK * 128];
// Pre-transposed bf16 weights
__device__ __nv_bfloat16 g_wqkv[384 * 64];   // [a][f]
__device__ __nv_bfloat16 g_wo[64 * 128];     // [f][a]
__device__ __nv_bfloat16 g_w1[128 * 64];     // [a][f]
__device__ __nv_bfloat16 g_w2[64 * 128];     // [f][a]

__device__ __forceinline__ int x_off(int tok, int f) {
    int dd = tok & 3;
    int nn = (tok >> 2) & 3;
    int tt = (tok >> 4) & 3;
    int v  = (tok >> 6) & 1;
    int n  = (tok >> 7) & 255;
    int Tt = (tok >> 15) & 1;
    return ((((v * 8 + Tt * 4 + tt) * 1024) + (n * 4 + nn)) * 4 + dd) * 64 + f;
}

__device__ __forceinline__ unsigned pack_bf2(float a, float b) {
    __nv_bfloat162 h = __floats2bfloat162_rn(a, b);
    return *(unsigned*)&h;
}

__device__ __forceinline__ void mma_bf16(float c[4], const unsigned a[4], const unsigned b[2]) {
    asm volatile("mma.sync.aligned.m16n8k16.row.col.f32.bf16.bf16.f32 "
                 "{%0,%1,%2,%3}, {%4,%5,%6,%7}, {%8,%9}, {%0,%1,%2,%3};"
                 : "+f"(c[0]), "+f"(c[1]), "+f"(c[2]), "+f"(c[3])
                 : "r"(a[0]), "r"(a[1]), "r"(a[2]), "r"(a[3]),
                   "r"(b[0]), "r"(b[1]));
}

__device__ __forceinline__ float wsum(float v) {
#pragma unroll
    for (int o = 16; o; o >>= 1) v += __shfl_xor_sync(0xffffffffu, v, o);
    return v;
}

__device__ __forceinline__ float tanh_fast(float x) {
    float y;
    asm("tanh.approx.f32 %0, %1;" : "=f"(y) : "f"(x));
    return y;
}

// ================= Kernel 0: weight prep (fp32 -> transposed bf16) =================
__global__ __launch_bounds__(256) void k_prep(const float* __restrict__ Wq,
                                              const float* __restrict__ Wkv,
                                              const float* __restrict__ Wo,
                                              const float* __restrict__ W1,
                                              const float* __restrict__ W2) {
    int idx = blockIdx.x * 256 + threadIdx.x;   // 0 .. 49151
    if (idx < 24576) {
        int a = idx >> 6, f = idx & 63;
        float w = (a < 128) ? Wq[f * 128 + a] : Wkv[f * 256 + a - 128];
        g_wqkv[idx] = __float2bfloat16(w);
    } else if (idx < 32768) {
        int j = idx - 24576;
        int f = j >> 7, a = j & 127;
        g_wo[j] = __float2bfloat16(Wo[a * 64 + f]);
    } else if (idx < 40960) {
        int j = idx - 32768;
        int a = j >> 6, f = j & 63;
        g_w1[j] = __float2bfloat16(W1[f * 128 + a]);
    } else {
        int j = idx - 40960;
        int f = j >> 7, a = j & 127;
        g_w2[j] = __float2bfloat16(W2[a * 64 + f]);
    }
}

// ================= Kernel 1: LN1 + qkv projection (MMA, W in registers) =================
#define HSTR 72
__global__ __launch_bounds__(256) void k_lnproj(const float* __restrict__ x,
                                                const float* __restrict__ ln1s,
                                                const float* __restrict__ ln1b,
                                                const float* __restrict__ bkv) {
    __shared__ __nv_bfloat16 hs[128 * HSTR];
    int t0 = blockIdx.x * 128;
    int tid = threadIdx.x;
    int wid = tid >> 5, lane = tid & 31;
    int g = lane >> 2, tq = lane & 3;
    int nbase = wid * 48;

    // B fragments (weights) -> registers, L1-hot
    unsigned wf[6][4][2];
#pragma unroll
    for (int nt = 0; nt < 6; nt++) {
        int col = nbase + nt * 8 + g;
#pragma unroll
        for (int kc = 0; kc < 4; kc++) {
            wf[nt][kc][0] = *(const unsigned*)&g_wqkv[col * 64 + kc * 16 + 2 * tq];
            wf[nt][kc][1] = *(const unsigned*)&g_wqkv[col * 64 + kc * 16 + 2 * tq + 8];
        }
    }

    if (tid < 128) {
        const float* xp = &x[x_off(t0 + tid, 0)];
        float v[64];
        float sum = 0.f;
#pragma unroll
        for (int i = 0; i < 16; i++) {
            float4 a = *(const float4*)(xp + 4 * i);
            v[4 * i] = a.x; v[4 * i + 1] = a.y; v[4 * i + 2] = a.z; v[4 * i + 3] = a.w;
            sum += a.x + a.y + a.z + a.w;
        }
        float mean = sum * (1.f / 64.f), var = 0.f;
#pragma unroll
        for (int i = 0; i < 64; i++) { float d = v[i] - mean; var += d * d; }
        float inv = rsqrtf(var * (1.f / 64.f) + 1e-5f);
#pragma unroll
        for (int i = 0; i < 64; i++)
            hs[tid * HSTR + i] = __float2bfloat16((v[i] - mean) * inv * ln1s[i] + ln1b[i]);
    }
    __syncthreads();

    for (int m = 0; m < 8; m++) {
        unsigned af[4][4];
        int r0 = m * 16 + g;
#pragma unroll
        for (int kc = 0; kc < 4; kc++) {
            af[kc][0] = *(const unsigned*)&hs[r0 * HSTR + kc * 16 + 2 * tq];
            af[kc][1] = *(const unsigned*)&hs[(r0 + 8) * HSTR + kc * 16 + 2 * tq];
            af[kc][2] = *(const unsigned*)&hs[r0 * HSTR + kc * 16 + 2 * tq + 8];
            af[kc][3] = *(const unsigned*)&hs[(r0 + 8) * HSTR + kc * 16 + 2 * tq + 8];
        }
#pragma unroll
        for (int nt = 0; nt < 6; nt++) {
            float c[4] = {0.f, 0.f, 0.f, 0.f};
#pragma unroll
            for (int kc = 0; kc < 4; kc++) mma_bf16(c, af[kc], wf[nt][kc]);
            int a0 = nbase + nt * 8 + 2 * tq;
            int row0 = t0 + m * 16 + g;
            if (a0 < 128) {
                *(unsigned*)&g_q[row0 * 128 + a0]       = pack_bf2(c[0], c[1]);
                *(unsigned*)&g_q[(row0 + 8) * 128 + a0] = pack_bf2(c[2], c[3]);
            } else {
                float b0 = bkv[a0 - 128], b1 = bkv[a0 - 127];
                int cc = a0 - 128;
                if (cc < 128) {
                    *(unsigned*)&g_k[row0 * 128 + cc]       = pack_bf2(c[0] + b0, c[1] + b1);
                    *(unsigned*)&g_k[(row0 + 8) * 128 + cc] = pack_bf2(c[2] + b0, c[3] + b1);
                } else {
                    *(unsigned*)&g_v[row0 * 128 + cc - 128]       = pack_bf2(c[0] + b0, c[1] + b1);
                    *(unsigned*)&g_v[(row0 + 8) * 128 + cc - 128] = pack_bf2(c[2] + b0, c[3] + b1);
                }
            }
        }
    }
}

// ================= Kernel 2: attention (register flash, no-max softmax) =================
#define KSTR 40
#define VSTR 72
__global__ __launch_bounds__(128) void k_attn(const float* __restrict__ bkv) {
    __shared__ __nv_bfloat16 Ks[64 * KSTR];
    __shared__ __nv_bfloat16 Vt[32 * VSTR];   // Vt[ch][kv]

    int w = blockIdx.x >> 2, head = blockIdx.x & 3;
    int Tt = w >> 8, n = w & 255;
    int tid = threadIdx.x, wid = tid >> 5, lane = tid & 31;
    int g = lane >> 2, tq = lane & 3;

    // Q fragments direct from global
    unsigned qf[2][2][4];
    {
        int base = w * 128 + wid * 32;
#pragma unroll
        for (int m = 0; m < 2; m++) {
            const __nv_bfloat16* q0 = &g_q[(base + m * 16 + g) * 128 + head * 32];
            const __nv_bfloat16* q1 = &g_q[(base + m * 16 + g + 8) * 128 + head * 32];
#pragma unroll
            for (int kc = 0; kc < 2; kc++) {
                qf[m][kc][0] = *(const unsigned*)&q0[kc * 16 + 2 * tq];
                qf[m][kc][1] = *(const unsigned*)&q1[kc * 16 + 2 * tq];
                qf[m][kc][2] = *(const unsigned*)&q0[kc * 16 + 2 * tq + 8];
                qf[m][kc][3] = *(const unsigned*)&q1[kc * 16 + 2 * tq + 8];
            }
        }
    }

    float O[2][4][4];
#pragma unroll
    for (int m = 0; m < 2; m++)
#pragma unroll
        for (int nt = 0; nt < 4; nt++)
#pragma unroll
            for (int i = 0; i < 4; i++) O[m][nt][i] = 0.f;
    float lr[2][2] = {{0.f, 0.f}, {0.f, 0.f}};

    int jrow = tid >> 1, halfc = (tid & 1) * 16;

    for (int tile = 0; tile < 8; tile++) {
        __syncthreads();
        // ---- load 64 kv rows with halo decode; V transposed ----
        {
            int skv = tile * 64 + jrow;
            int d2 = skv & 7, nn2 = (skv >> 3) & 3, t2 = (skv >> 5) & 7, vv = (skv >> 8) & 1;
            bool pad = (d2 < 2) || (d2 >= 6);
            int Ttp = Tt, tt;
            if (t2 < 2)       { Ttp = Tt - 1; tt = t2 + 2; }
            else if (t2 >= 6) { Ttp = Tt + 1; tt = t2 - 6; }
            else              { tt = t2 - 2; }
            if (Ttp < 0 || Ttp >= 2) pad = true;
            if (pad) {
#pragma unroll
                for (int c = 0; c < 16; c++) {
                    Ks[jrow * KSTR + halfc + c]   = __float2bfloat16(bkv[head * 32 + halfc + c]);
                    Vt[(halfc + c) * VSTR + jrow] = __float2bfloat16(bkv[128 + head * 32 + halfc + c]);
                }
            } else {
                int tokp = ((Ttp * 256 + n) * 128) + ((vv * 4 + tt) * 4 + nn2) * 4 + (d2 - 2);
                const __nv_bfloat16* kp = &g_k[tokp * 128 + head * 32 + halfc];
                const __nv_bfloat16* vp = &g_v[tokp * 128 + head * 32 + halfc];
#pragma unroll
                for (int c = 0; c < 16; c += 2)
                    *(unsigned*)&Ks[jrow * KSTR + halfc + c] = *(const unsigned*)&kp[c];
#pragma unroll
                for (int c = 0; c < 16; c++)
                    Vt[(halfc + c) * VSTR + jrow] = vp[c];
            }
        }
        __syncthreads();

#pragma unroll
        for (int kc = 0; kc < 4; kc++) {
            // S fragments for kv columns kc*16 .. kc*16+15 (two 8-wide tiles)
            unsigned bl[2][2], bh[2][2];
#pragma unroll
            for (int c2 = 0; c2 < 2; c2++) {
                bl[c2][0] = *(const unsigned*)&Ks[(kc * 16 + g) * KSTR + c2 * 16 + 2 * tq];
                bl[c2][1] = *(const unsigned*)&Ks[(kc * 16 + g) * KSTR + c2 * 16 + 2 * tq + 8];
                bh[c2][0] = *(const unsigned*)&Ks[(kc * 16 + 8 + g) * KSTR + c2 * 16 + 2 * tq];
                bh[c2][1] = *(const unsigned*)&Ks[(kc * 16 + 8 + g) * KSTR + c2 * 16 + 2 * tq + 8];
            }
            unsigned pf[2][4];
#pragma unroll
            for (int m = 0; m < 2; m++) {
                float cl[4] = {0.f, 0.f, 0.f, 0.f};
                float ch[4] = {0.f, 0.f, 0.f, 0.f};
#pragma unroll
                for (int c2 = 0; c2 < 2; c2++) {
                    mma_bf16(cl, qf[m][c2], bl[c2]);
                    mma_bf16(ch, qf[m][c2], bh[c2]);
                }
                float e0 = __expf(cl[0] * SCALE), e1 = __expf(cl[1] * SCALE);
                float e2 = __expf(cl[2] * SCALE), e3 = __expf(cl[3] * SCALE);
                float f0 = __expf(ch[0] * SCALE), f1 = __expf(ch[1] * SCALE);
                float f2 = __expf(ch[2] * SCALE), f3 = __expf(ch[3] * SCALE);
                lr[m][0] += e0 + e1 + f0 + f1;
                lr[m][1] += e2 + e3 + f2 + f3;
                pf[m][0] = pack_bf2(e0, e1);
                pf[m][1] = pack_bf2(e2, e3);
                pf[m][2] = pack_bf2(f0, f1);
                pf[m][3] = pack_bf2(f2, f3);
            }
            // O += P V
#pragma unroll
            for (int nt = 0; nt < 4; nt++) {
                unsigned vf[2];
                vf[0] = *(const unsigned*)&Vt[(nt * 8 + g) * VSTR + kc * 16 + 2 * tq];
                vf[1] = *(const unsigned*)&Vt[(nt * 8 + g) * VSTR + kc * 16 + 2 * tq + 8];
                mma_bf16(O[0][nt], pf[0], vf);
                mma_bf16(O[1][nt], pf[1], vf);
            }
        }
    }

    // finish: quad-reduce row sums, normalize, store bf16
#pragma unroll
    for (int m = 0; m < 2; m++) {
#pragma unroll
        for (int r = 0; r < 2; r++) {
            lr[m][r] += __shfl_xor_sync(0xffffffffu, lr[m][r], 1);
            lr[m][r] += __shfl_xor_sync(0xffffffffu, lr[m][r], 2);
        }
        float i0 = 1.f / lr[m][0], i1 = 1.f / lr[m][1];
        int sq0 = w * 128 + wid * 32 + m * 16 + g;
#pragma unroll
        for (int nt = 0; nt < 4; nt++) {
            int ch = head * 32 + nt * 8 + 2 * tq;
            *(unsigned*)&g_o[sq0 * 128 + ch]       = pack_bf2(O[m][nt][0] * i0, O[m][nt][1] * i0);
            *(unsigned*)&g_o[(sq0 + 8) * 128 + ch] = pack_bf2(O[m][nt][2] * i1, O[m][nt][3] * i1);
        }
    }
}

// ================= Kernel 3: epilogue (MMA) =================
#define OSTR  136   // bf16 stride for os/gs buffer
#define TSTR  68    // fp32 stride for toks
#define H2STR 72
#define EPI_SMEM (128 * OSTR * 2 + 128 * TSTR * 4 + 128 * H2STR * 2)

__global__ __launch_bounds__(256) void k_epi(const float* __restrict__ x,
                                             const float* __restrict__ bo,
                                             const float* __restrict__ gamma,
                                             const float* __restrict__ ln2s,
                                             const float* __restrict__ ln2b,
                                             const float* __restrict__ b1,
                                             const float* __restrict__ b2,
                                             const float* __restrict__ gmlp,
                                             float* __restrict__ out) {
    extern __shared__ char smbase[];
    __nv_bfloat16* osgs = (__nv_bfloat16*)smbase;                          // [128][OSTR]
    float* toks = (float*)(smbase + 128 * OSTR * 2);                       // [128][TSTR]
    __nv_bfloat16* h2s = (__nv_bfloat16*)(smbase + 128 * OSTR * 2 + 128 * TSTR * 4);

    int t0 = blockIdx.x * 128;
    int tid = threadIdx.x;
    int wid = tid >> 5, lane = tid & 31;
    int g = lane >> 2, tq = lane & 3;

    // load o (bf16) and x (fp32, residual)
    for (int i = tid; i < 128 * 64; i += 256) {
        int row = i >> 6, cp = i & 63;
        *(unsigned*)&osgs[row * OSTR + cp * 2] = ((const unsigned*)g_o)[t0 * 64 + i];
    }
    for (int i = tid; i < 128 * 64; i += 256) {
        int t = i >> 6, f = i & 63;
        toks[t * TSTR + f] = x[x_off(t0 + t, f)];
    }
    __syncthreads();

    // ---- GEMM1: upd = o @ Wo; toks += gamma*(upd+bo) ----
    {
        int fcol = wid * 8 + g;
        unsigned wf[8][2];
#pragma unroll
        for (int kc = 0; kc < 8; kc++) {
            wf[kc][0] = *(const unsigned*)&g_wo[fcol * 128 + kc * 16 + 2 * tq];
            wf[kc][1] = *(const unsigned*)&g_wo[fcol * 128 + kc * 16 + 2 * tq + 8];
        }
        int c0 = wid * 8 + 2 * tq;
        float gm0 = gamma[c0], gm1 = gamma[c0 + 1];
        float bo0 = bo[c0], bo1 = bo[c0 + 1];
        for (int m = 0; m < 8; m++) {
            float c[4] = {0.f, 0.f, 0.f, 0.f};
            int r0 = m * 16 + g;
#pragma unroll
            for (int kc = 0; kc < 8; kc++) {
                unsigned af[4];
                af[0] = *(const unsigned*)&osgs[r0 * OSTR + kc * 16 + 2 * tq];
                af[1] = *(const unsigned*)&osgs[(r0 + 8) * OSTR + kc * 16 + 2 * tq];
                af[2] = *(const unsigned*)&osgs[r0 * OSTR + kc * 16 + 2 * tq + 8];
                af[3] = *(const unsigned*)&osgs[(r0 + 8) * OSTR + kc * 16 + 2 * tq + 8];
                mma_bf16(c, af, wf[kc]);
            }
            toks[r0 * TSTR + c0]           += gm0 * (c[0] + bo0);
            toks[r0 * TSTR + c0 + 1]       += gm1 * (c[1] + bo1);
            toks[(r0 + 8) * TSTR + c0]     += gm0 * (c[2] + bo0);
            toks[(r0 + 8) * TSTR + c0 + 1] += gm1 * (c[3] + bo1);
        }
    }
    __syncthreads();

    // ---- LN2 ----
    {
        float s0 = ln2s[lane], s1 = ln2s[lane + 32];
        float bb0 = ln2b[lane], bb1 = ln2b[lane + 32];
#pragma unroll
        for (int k = 0; k < 16; k++) {
            int t = wid * 16 + k;
            float a0 = toks[t * TSTR + lane], a1 = toks[t * TSTR + lane + 32];
            float mm = wsum(a0 + a1) * (1.f / 64.f);
            float d0 = a0 - mm, d1 = a1 - mm;
            float var = wsum(d0 * d0 + d1 * d1) * (1.f / 64.f);
            float inv = rsqrtf(var + 1e-5f);
            h2s[t * H2STR + lane]      = __float2bfloat16(d0 * inv * s0 + bb0);
            h2s[t * H2STR + lane + 32] = __float2bfloat16(d1 * inv * s1 + bb1);
        }
    }
    __syncthreads();

    // ---- GEMM2: hidden = gelu(h2 @ W1 + b1) -> osgs (reused) ----
    {
        unsigned wf[2][4][2];
        float bb[2][2];
#pragma unroll
        for (int nt = 0; nt < 2; nt++) {
            int acol = wid * 16 + nt * 8 + g;
#pragma unroll
            for (int kc = 0; kc < 4; kc++) {
                wf[nt][kc][0] = *(const unsigned*)&g_w1[acol * 64 + kc * 16 + 2 * tq];
                wf[nt][kc][1] = *(const unsigned*)&g_w1[acol * 64 + kc * 16 + 2 * tq + 8];
            }
            bb[nt][0] = b1[wid * 16 + nt * 8 + 2 * tq];
            bb[nt][1] = b1[wid * 16 + nt * 8 + 2 * tq + 1];
        }
        for (int m = 0; m < 8; m++) {
            int r0 = m * 16 + g;
            unsigned af[4][4];
#pragma unroll
            for (int kc = 0; kc < 4; kc++) {
                af[kc][0] = *(const unsigned*)&h2s[r0 * H2STR + kc * 16 + 2 * tq];
                af[kc][1] = *(const unsigned*)&h2s[(r0 + 8) * H2STR + kc * 16 + 2 * tq];
                af[kc][2] = *(const unsigned*)&h2s[r0 * H2STR + kc * 16 + 2 * tq + 8];
                af[kc][3] = *(const unsigned*)&h2s[(r0 + 8) * H2STR + kc * 16 + 2 * tq + 8];
            }
#pragma unroll
            for (int nt = 0; nt < 2; nt++) {
                float c[4] = {0.f, 0.f, 0.f, 0.f};
#pragma unroll
                for (int kc = 0; kc < 4; kc++) mma_bf16(c, af[kc], wf[nt][kc]);
                float gz[4];
#pragma unroll
                for (int i = 0; i < 4; i++) {
                    float z = c[i] + bb[nt][i & 1];
                    float u = 0.7978845608028654f * (z + 0.044715f * z * z * z);
                    gz[i] = 0.5f * z * (1.f + tanh_fast(u));
                }
                int col = wid * 16 + nt * 8 + 2 * tq;
                *(unsigned*)&osgs[r0 * OSTR + col]       = pack_bf2(gz[0], gz[1]);
                *(unsigned*)&osgs[(r0 + 8) * OSTR + col] = pack_bf2(gz[2], gz[3]);
            }
        }
    }
    __syncthreads();

    // ---- GEMM3: out = toks + gmlp*(hidden @ W2 + b2), transposed store ----
    {
        int fcol = wid * 8 + g;
        unsigned wf[8][2];
#pragma unroll
        for (int kc = 0; kc < 8; kc++) {
            wf[kc][0] = *(const unsigned*)&g_w2[fcol * 128 + kc * 16 + 2 * tq];
            wf[kc][1] = *(const unsigned*)&g_w2[fcol * 128 + kc * 16 + 2 * tq + 8];
        }
        int c0 = wid * 8 + 2 * tq;
        float gm0 = gmlp[c0], gm1 = gmlp[c0 + 1];
        float b20 = b2[c0], b21 = b2[c0 + 1];
        for (int m = 0; m < 8; m++) {
            float c[4] = {0.f, 0.f, 0.f, 0.f};
            int r0 = m * 16 + g;
#pragma unroll
            for (int kc = 0; kc < 8; kc++) {
                unsigned af[4];
                af[0] = *(const unsigned*)&osgs[r0 * OSTR + kc * 16 + 2 * tq];
                af[1] = *(const unsigned*)&osgs[(r0 + 8) * OSTR + kc * 16 + 2 * tq];
                af[2] = *(const unsigned*)&osgs[r0 * OSTR + kc * 16 + 2 * tq + 8];
                af[3] = *(const unsigned*)&osgs[(r0 + 8) * OSTR + kc * 16 + 2 * tq + 8];
                mma_bf16(c, af, wf[kc]);
            }
            int tokA = t0 + r0, tokB = t0 + r0 + 8;
            float2 vA = make_float2(toks[r0 * TSTR + c0] + gm0 * (c[0] + b20),
                                    toks[r0 * TSTR + c0 + 1] + gm1 * (c[1] + b21));
            float2 vB = make_float2(toks[(r0 + 8) * TSTR + c0] + gm0 * (c[2] + b20),
                                    toks[(r0 + 8) * TSTR + c0 + 1] + gm1 * (c[3] + b21));
            *(float2*)&out[x_off(tokA, c0)] = vA;
            *(float2*)&out[x_off(tokB, c0)] = vB;
        }
    }
}

extern "C" void kernel_launch(void* const* d_in, const int* in_sizes, int n_in,
                              void* d_out, int out_size) {
    const float* x     = (const float*)d_in[0];
    const float* ln1_s = (const float*)d_in[1];
    const float* ln1_b = (const float*)d_in[2];
    const float* Wq    = (const float*)d_in[3];
    const float* Wkv   = (const float*)d_in[4];
    const float* bkv   = (const float*)d_in[5];
    const float* Wo    = (const float*)d_in[6];
    const float* bo    = (const float*)d_in[7];
    const float* gamma = (const float*)d_in[8];
    const float* ln2s  = (const float*)d_in[9];
    const float* ln2b  = (const float*)d_in[10];
    const float* W1    = (const float*)d_in[11];
    const float* b1    = (const float*)d_in[12];
    const float* W2    = (const float*)d_in[13];
    const float* b2    = (const float*)d_in[14];
    const float* gmlp  = (const float*)d_in[15];
    float* out = (float*)d_out;

    static int epi_cfg = 0;
    if (!epi_cfg) {
        cudaFuncSetAttribute(k_epi, cudaFuncAttributeMaxDynamicSharedMemorySize, EPI_SMEM);
        epi_cfg = 1;
    }

    k_prep  <<<192, 256>>>(Wq, Wkv, Wo, W1, W2);
    k_lnproj<<<NTOK / 128, 256>>>(x, ln1_s, ln1_b, bkv);
    k_attn  <<<NWIN * NHEAD, 128>>>(bkv);
    k_epi   <<<NTOK / 128, 256, EPI_SMEM>>>(x, bo, gamma, ln2s, ln2b, b1, b2, gmlp, out);
}